// round 1
// baseline (speedup 1.0000x reference)
#include <cuda_runtime.h>

#define N_NODES   100000
#define N_EDGES   1600000
#define N_GRAPHS  5000
#define ND        16
#define ED        16
#define HID       20
#define H2        10

// Scratch (static __device__ allocations — allowed; no cudaMalloc)
__device__ float g_x [N_NODES * HID];   // scatter-sum of messages per node
__device__ float g_pa[N_NODES * HID];   // node_attr @ W_msg[0:16]
__device__ float g_pb[N_NODES * HID];   // node_attr @ W_msg[16:32]
__device__ float g_g [N_GRAPHS * H2];   // graph pooled features

// ---------------------------------------------------------------------------
// Kernel 1: zero the accumulators (graph replays must start from zero)
// ---------------------------------------------------------------------------
__global__ void zero_kernel() {
    const float4 z = make_float4(0.f, 0.f, 0.f, 0.f);
    int stride = gridDim.x * blockDim.x;
    int i = blockIdx.x * blockDim.x + threadIdx.x;
    const int x4 = (N_NODES * HID) / 4;          // 500000
    for (int j = i; j < x4; j += stride) ((float4*)g_x)[j] = z;
    const int g4 = (N_GRAPHS * H2) / 4;          // 12500
    for (int j = i; j < g4; j += stride) ((float4*)g_g)[j] = z;
}

// ---------------------------------------------------------------------------
// Kernel 2: per-node projections pa = A@Wa, pb = A@Wb
// ---------------------------------------------------------------------------
__global__ void node_proj_kernel(const float* __restrict__ node_attr,
                                 const float* __restrict__ W_msg) {
    __shared__ float sWa[ND * HID];
    __shared__ float sWb[ND * HID];
    for (int i = threadIdx.x; i < ND * HID; i += blockDim.x) {
        sWa[i] = W_msg[i];                  // rows 0:16
        sWb[i] = W_msg[ND * HID + i];       // rows 16:32
    }
    __syncthreads();

    int n = blockIdx.x * blockDim.x + threadIdx.x;
    if (n >= N_NODES) return;

    float a[ND];
    const float4* ap = (const float4*)(node_attr + (size_t)n * ND);
#pragma unroll
    for (int q = 0; q < 4; q++) {
        float4 v = ap[q];
        a[4*q+0] = v.x; a[4*q+1] = v.y; a[4*q+2] = v.z; a[4*q+3] = v.w;
    }

    float acc[HID];
#pragma unroll
    for (int j = 0; j < HID; j++) acc[j] = 0.f;
#pragma unroll
    for (int k = 0; k < ND; k++)
#pragma unroll
        for (int j = 0; j < HID; j++) acc[j] = fmaf(a[k], sWa[k * HID + j], acc[j]);
    float4* pa = (float4*)(g_pa + (size_t)n * HID);
#pragma unroll
    for (int q = 0; q < 5; q++)
        pa[q] = make_float4(acc[4*q], acc[4*q+1], acc[4*q+2], acc[4*q+3]);

#pragma unroll
    for (int j = 0; j < HID; j++) acc[j] = 0.f;
#pragma unroll
    for (int k = 0; k < ND; k++)
#pragma unroll
        for (int j = 0; j < HID; j++) acc[j] = fmaf(a[k], sWb[k * HID + j], acc[j]);
    float4* pb = (float4*)(g_pb + (size_t)n * HID);
#pragma unroll
    for (int q = 0; q < 5; q++)
        pb[q] = make_float4(acc[4*q], acc[4*q+1], acc[4*q+2], acc[4*q+3]);
}

// ---------------------------------------------------------------------------
// Kernel 3: edge message + scatter-sum (the heavy one)
//   msg = relu(pa[src] + pb[dst] + edge_attr[e]@We + b_msg)
//   g_x[dst] += msg  via red.global.add.v4.f32
// ---------------------------------------------------------------------------
__global__ void edge_kernel(const int*   __restrict__ edge_index,
                            const float* __restrict__ edge_attr,
                            const float* __restrict__ W_msg,
                            const float* __restrict__ b_msg) {
    __shared__ float sWe[ED * HID];
    __shared__ float sb[HID];
    for (int i = threadIdx.x; i < ED * HID; i += blockDim.x)
        sWe[i] = W_msg[2 * ND * HID + i];   // rows 32:48
    for (int i = threadIdx.x; i < HID; i += blockDim.x)
        sb[i] = b_msg[i];
    __syncthreads();

    int e = blockIdx.x * blockDim.x + threadIdx.x;
    if (e >= N_EDGES) return;

    int src = edge_index[e];
    int dst = edge_index[N_EDGES + e];

    float acc[HID];
#pragma unroll
    for (int j = 0; j < HID; j++) acc[j] = sb[j];

    const float4* ep = (const float4*)(edge_attr + (size_t)e * ED);
#pragma unroll
    for (int q = 0; q < 4; q++) {
        float4 v = ep[q];
        float ek[4] = {v.x, v.y, v.z, v.w};
#pragma unroll
        for (int t = 0; t < 4; t++)
#pragma unroll
            for (int j = 0; j < HID; j++)
                acc[j] = fmaf(ek[t], sWe[(4*q + t) * HID + j], acc[j]);
    }

    const float4* pa = (const float4*)(g_pa + (size_t)src * HID);
    const float4* pb = (const float4*)(g_pb + (size_t)dst * HID);
#pragma unroll
    for (int q = 0; q < 5; q++) {
        float4 va = pa[q];
        float4 vb = pb[q];
        acc[4*q+0] += va.x + vb.x;
        acc[4*q+1] += va.y + vb.y;
        acc[4*q+2] += va.z + vb.z;
        acc[4*q+3] += va.w + vb.w;
    }

#pragma unroll
    for (int j = 0; j < HID; j++) acc[j] = fmaxf(acc[j], 0.f);

    float* xr = g_x + (size_t)dst * HID;   // 80B rows -> every 16B chunk aligned
#pragma unroll
    for (int q = 0; q < 5; q++) {
        asm volatile("red.global.add.v4.f32 [%0], {%1,%2,%3,%4};"
                     :: "l"(xr + 4*q),
                        "f"(acc[4*q]), "f"(acc[4*q+1]),
                        "f"(acc[4*q+2]), "f"(acc[4*q+3])
                     : "memory");
    }
}

// ---------------------------------------------------------------------------
// Kernel 4: node MLP relu(x@W1+b1) + graph pooling via red.v2.f32
// ---------------------------------------------------------------------------
__global__ void node_mlp_kernel(const int*   __restrict__ batch,
                                const float* __restrict__ W1,
                                const float* __restrict__ b1) {
    __shared__ float sW[HID * H2];
    __shared__ float sb[H2];
    for (int i = threadIdx.x; i < HID * H2; i += blockDim.x) sW[i] = W1[i];
    for (int i = threadIdx.x; i < H2; i += blockDim.x) sb[i] = b1[i];
    __syncthreads();

    int n = blockIdx.x * blockDim.x + threadIdx.x;
    if (n >= N_NODES) return;

    float x[HID];
    const float4* xp = (const float4*)(g_x + (size_t)n * HID);
#pragma unroll
    for (int q = 0; q < 5; q++) {
        float4 v = xp[q];
        x[4*q+0] = v.x; x[4*q+1] = v.y; x[4*q+2] = v.z; x[4*q+3] = v.w;
    }

    float y[H2];
#pragma unroll
    for (int j = 0; j < H2; j++) y[j] = sb[j];
#pragma unroll
    for (int k = 0; k < HID; k++)
#pragma unroll
        for (int j = 0; j < H2; j++) y[j] = fmaf(x[k], sW[k * H2 + j], y[j]);
#pragma unroll
    for (int j = 0; j < H2; j++) y[j] = fmaxf(y[j], 0.f);

    int b = batch[n];
    float* gr = g_g + (size_t)b * H2;      // 40B rows -> every 8B chunk aligned
#pragma unroll
    for (int q = 0; q < 5; q++) {
        asm volatile("red.global.add.v2.f32 [%0], {%1,%2};"
                     :: "l"(gr + 2*q), "f"(y[2*q]), "f"(y[2*q+1])
                     : "memory");
    }
}

// ---------------------------------------------------------------------------
// Kernel 5: graph MLP: out = relu(g@W2+b2) @ W3 + b3
// ---------------------------------------------------------------------------
__global__ void graph_mlp_kernel(const float* __restrict__ W2,
                                 const float* __restrict__ b2,
                                 const float* __restrict__ W3,
                                 const float* __restrict__ b3,
                                 float* __restrict__ out) {
    __shared__ float sW2[H2 * H2];
    __shared__ float sb2[H2];
    __shared__ float sW3[H2];
    __shared__ float sb3;
    for (int i = threadIdx.x; i < H2 * H2; i += blockDim.x) sW2[i] = W2[i];
    if (threadIdx.x < H2) { sb2[threadIdx.x] = b2[threadIdx.x]; sW3[threadIdx.x] = W3[threadIdx.x]; }
    if (threadIdx.x == 0) sb3 = b3[0];
    __syncthreads();

    int g = blockIdx.x * blockDim.x + threadIdx.x;
    if (g >= N_GRAPHS) return;

    float v[H2];
    const float2* gp = (const float2*)(g_g + (size_t)g * H2);
#pragma unroll
    for (int q = 0; q < 5; q++) {
        float2 t = gp[q];
        v[2*q] = t.x; v[2*q+1] = t.y;
    }

    float o = sb3;
#pragma unroll
    for (int j = 0; j < H2; j++) {
        float h = sb2[j];
#pragma unroll
        for (int k = 0; k < H2; k++) h = fmaf(v[k], sW2[k * H2 + j], h);
        o = fmaf(fmaxf(h, 0.f), sW3[j], o);
    }
    out[g] = o;
}

// ---------------------------------------------------------------------------
extern "C" void kernel_launch(void* const* d_in, const int* in_sizes, int n_in,
                              void* d_out, int out_size) {
    const int*   edge_index = (const int*)  d_in[0];
    const float* node_attr  = (const float*)d_in[1];
    const float* edge_attr  = (const float*)d_in[2];
    const int*   batch      = (const int*)  d_in[3];
    const float* W_msg      = (const float*)d_in[4];
    const float* b_msg      = (const float*)d_in[5];
    const float* W1         = (const float*)d_in[6];
    const float* b1         = (const float*)d_in[7];
    const float* W2         = (const float*)d_in[8];
    const float* b2         = (const float*)d_in[9];
    const float* W3         = (const float*)d_in[10];
    const float* b3         = (const float*)d_in[11];
    float* out = (float*)d_out;

    zero_kernel<<<1024, 256>>>();
    node_proj_kernel<<<(N_NODES + 255) / 256, 256>>>(node_attr, W_msg);
    edge_kernel<<<(N_EDGES + 255) / 256, 256>>>(edge_index, edge_attr, W_msg, b_msg);
    node_mlp_kernel<<<(N_NODES + 255) / 256, 256>>>(batch, W1, b1);
    graph_mlp_kernel<<<(N_GRAPHS + 255) / 256, 256>>>(W2, b2, W3, b3, out);
}